// round 11
// baseline (speedup 1.0000x reference)
#include <cuda_runtime.h>
#include <cuda_fp16.h>
#include <cstdint>

// ---------------- problem constants ----------------
#define KH_ 9
#define KW_ 9
#define IC_ 25
#define OC_ 100
#define H_  256
#define W_  256
#define OH_ 248
#define OW_ 248
#define B_  8

// ---------------- GEMM config ----------------
#define KWP 10            // kw padded 9 -> 10
#define NOC 104           // oc padded 100 -> 104 (13 n8 chunks: 7 + 6 per warp col)
#define MT  128           // pixels per tile
#define NTHR 256

// quarter tiles (A and B share geometry): 64 k-elems, pitch 72 = 144 B
#define QPITCH 72
#define QROWB  144
#define BQTILE (NOC*QROWB)        // 14976 B
#define AQTILE (MT*QROWB)         // 18432 B
#define SEGB   (AQTILE + BQTILE)  // 33408 B per ring slot
#define NSEG   36                 // 9 kh * 4 quarters

// smem layout (bytes)
#define SM_BIAS 0
#define SM_RING 512
#define SMEM_TOTAL (SM_RING + 3*SEGB)   // 512 + 100224 = 100736 -> 2 CTAs/SM

// fp16 weights: [kh][quarter][oc][k_local(72)]
__device__ __align__(16) __half g_w[KH_][4][NOC][QPITCH];
// kw-expanded fp16 input: [b][input row][strip][quarter][px][k_local(72)]  (~302 MB)
__device__ __align__(16) __half g_a2[B_][H_][2][4][MT][QPITCH];

// ---------------- helpers ----------------
__device__ __forceinline__ uint32_t smem_u32(const void* p) {
    uint32_t a;
    asm("{ .reg .u64 t; cvta.to.shared.u64 t, %1; cvt.u32.u64 %0, t; }" : "=r"(a) : "l"(p));
    return a;
}

__device__ __forceinline__ void ldmx4(uint32_t& r0, uint32_t& r1, uint32_t& r2,
                                      uint32_t& r3, uint32_t addr) {
    asm volatile("ldmatrix.sync.aligned.m8n8.x4.shared.b16 {%0,%1,%2,%3}, [%4];"
                 : "=r"(r0), "=r"(r1), "=r"(r2), "=r"(r3) : "r"(addr));
}

__device__ __forceinline__ void ldmx2(uint32_t& r0, uint32_t& r1, uint32_t addr) {
    asm volatile("ldmatrix.sync.aligned.m8n8.x2.shared.b16 {%0,%1}, [%2];"
                 : "=r"(r0), "=r"(r1) : "r"(addr));
}

__device__ __forceinline__ void mma16816(float* d, const uint32_t* a,
                                         uint32_t b0, uint32_t b1) {
    asm volatile(
        "mma.sync.aligned.m16n8k16.row.col.f32.f16.f16.f32 "
        "{%0,%1,%2,%3}, {%4,%5,%6,%7}, {%8,%9}, {%0,%1,%2,%3};"
        : "+f"(d[0]), "+f"(d[1]), "+f"(d[2]), "+f"(d[3])
        : "r"(a[0]), "r"(a[1]), "r"(a[2]), "r"(a[3]), "r"(b0), "r"(b1));
}

__device__ __forceinline__ void cpasync16(uint32_t dst, const void* src) {
    asm volatile("cp.async.cg.shared.global [%0], [%1], 16;"
                 :: "r"(dst), "l"(src));
}

// ---------------- prep: weights ----------------
__global__ void prep_w(const float* __restrict__ wt) {
    int idx = blockIdx.x * blockDim.x + threadIdx.x;
    const int n = KH_ * 4 * NOC * QPITCH;
    if (idx >= n) return;
    int kh   = idx / (4 * NOC * QPITCH);
    int rem  = idx % (4 * NOC * QPITCH);
    int q    = rem / (NOC * QPITCH);      rem %= (NOC * QPITCH);
    int oc   = rem / QPITCH;
    int kl   = rem % QPITCH;
    float w = 0.f;
    int k = q * 64 + kl;
    if (oc < OC_ && kl < 64 && k < IC_ * KWP) {
        int ic = k / KWP, kw = k % KWP;
        if (kw < KW_)
            w = wt[(((size_t)oc * IC_ + ic) * KH_ + kh) * KW_ + kw];
    }
    g_w[kh][q][oc][kl] = __float2half_rn(w);
}

// ---------------- prep: kw-expanded fp16 input ----------------
// One thread writes one 2-elem (uint32) pair: k-local pair (2j, 2j+1).
__global__ void prep_a(const float* __restrict__ pic) {
    const int idx = blockIdx.x * blockDim.x + threadIdx.x;
    const int total = B_ * H_ * 2 * 4 * MT * (QPITCH / 2);
    if (idx >= total) return;
    int j   = idx % (QPITCH / 2);
    int r1  = idx / (QPITCH / 2);
    int px  = r1 % MT;      r1 /= MT;
    int q   = r1 % 4;       r1 /= 4;
    int st  = r1 % 2;       r1 /= 2;
    int row = r1 % H_;
    int b   = r1 / H_;

    uint32_t packed = 0;
    int kl0 = 2 * j;
    if (kl0 < 64) {
        int k0 = q * 64 + kl0;         // even -> kw even (KWP=10)
        int ic = k0 / KWP;
        int kw = k0 - ic * KWP;        // in {0,2,4,6,8}
        int x0 = st * (OW_ - MT);      // 0 or 120
        const float* base = pic + (((size_t)(b * IC_ + ic)) * H_ + row) * W_;
        __half h0 = __float2half_rn((ic < IC_) ? base[x0 + px + kw] : 0.f);
        __half h1 = __float2half_rn((ic < IC_ && kw + 1 < KW_) ? base[x0 + px + kw + 1] : 0.f);
        packed = (uint32_t)__half_as_ushort(h0) | ((uint32_t)__half_as_ushort(h1) << 16);
    }
    *(uint32_t*)&g_a2[b][row][st][q][px][kl0] = packed;
}

// ---------------- main kernel ----------------
// block = 128 px x 104 oc of one output row (b, y).
// 8 warps: wm = wid&3 (2 m16-frags), wn = wid>>2 (7 or 6 n8-chunks).
// 36 segments: seg s -> kh=s>>2, quarter=s&3. Ring-3 slots each hold the
// A-quarter + B-quarter; cp.async prefetch at distance 2.
__global__ __launch_bounds__(NTHR, 2)
void conv_hmma(const float* __restrict__ bias,
               float* __restrict__ out) {
    extern __shared__ char smem[];
    const uint32_t sb = smem_u32(smem);
    const int tid = threadIdx.x;
    const int lid = tid & 31;
    const int wid = tid >> 5;
    const int wm = wid & 3;
    const int wn = wid >> 2;
    const int g  = lid >> 2;          // 0..7
    const int c4 = (lid & 3) << 1;    // 0,2,4,6
    const int st = blockIdx.x;        // strip 0 / 1
    const int x0 = st ? (OW_ - MT) : 0;
    const int y  = blockIdx.y;
    const int b  = blockIdx.z;

    if (tid < NOC)
        *(float*)(smem + SM_BIAS + tid * 4) = (tid < OC_) ? bias[tid] : 0.f;
    __syncthreads();

    // ---- prologue: issue groups for segments 0 and 1 ----
#pragma unroll
    for (int s = 0; s < 2; ++s) {
        const char* asrc = (const char*)(&g_a2[b][y + (s >> 2)][st][s & 3][0][0]);
        const char* bsrc = (const char*)(&g_w[s >> 2][s & 3][0][0]);
        const uint32_t slot = sb + SM_RING + (uint32_t)(s * SEGB);
#pragma unroll 1
        for (int i = tid; i < AQTILE / 16; i += NTHR)
            cpasync16(slot + (uint32_t)(i * 16), asrc + i * 16);
#pragma unroll 1
        for (int i = tid; i < BQTILE / 16; i += NTHR)
            cpasync16(slot + (uint32_t)(AQTILE + i * 16), bsrc + i * 16);
        asm volatile("cp.async.commit_group;" ::: "memory");
    }

    // A ldmatrix lane offsets: matrix layout rows 0-15 x k 0-15 per m-frag
    uint32_t aoff[2];
#pragma unroll
    for (int m = 0; m < 2; ++m)
        aoff[m] = (uint32_t)((((wm * 2 + m) * 16 + (lid & 15)) * QROWB)
                             + ((lid >> 4) & 1) * 16);

    // B ldmatrix offsets (within B tile)
    const int cb0 = wn * 7;        // base n8 chunk: 0 (7 chunks) or 7 (6 chunks)
    const int grp = lid >> 3;
    const int tr  = lid & 7;
    uint32_t bro[3];
#pragma unroll
    for (int j = 0; j < 3; ++j)
        bro[j] = (uint32_t)(AQTILE + ((cb0 + 2 * j + (grp >> 1)) * 8 + tr) * QROWB
                            + (grp & 1) * 16);
    const uint32_t brx = (uint32_t)(AQTILE + (6 * 8 + (lid & 7)) * QROWB
                                    + ((lid >> 3) & 1) * 16);   // chunk 6 (wn0 only)

    float acc[2][7][4];
#pragma unroll
    for (int m = 0; m < 2; ++m)
#pragma unroll
        for (int n = 0; n < 7; ++n)
#pragma unroll
            for (int q = 0; q < 4; ++q)
                acc[m][n][q] = 0.f;

    // ---- pipelined main loop ----
#pragma unroll 1
    for (int s = 0; s < NSEG; ++s) {
        if (s < NSEG - 2) {
            asm volatile("cp.async.wait_group 1;" ::: "memory");
        } else {
            asm volatile("cp.async.wait_group 0;" ::: "memory");
        }
        __syncthreads();

        // prefetch segment s+2
        if (s + 2 < NSEG) {
            const int s2 = s + 2;
            const char* asrc = (const char*)(&g_a2[b][y + (s2 >> 2)][st][s2 & 3][0][0]);
            const char* bsrc = (const char*)(&g_w[s2 >> 2][s2 & 3][0][0]);
            const uint32_t slot = sb + SM_RING + (uint32_t)((s2 % 3) * SEGB);
#pragma unroll 1
            for (int i = tid; i < AQTILE / 16; i += NTHR)
                cpasync16(slot + (uint32_t)(i * 16), asrc + i * 16);
#pragma unroll 1
            for (int i = tid; i < BQTILE / 16; i += NTHR)
                cpasync16(slot + (uint32_t)(AQTILE + i * 16), bsrc + i * 16);
            asm volatile("cp.async.commit_group;" ::: "memory");
        }

        // ---- compute: 4 kc chunks ----
        const uint32_t slot = sb + SM_RING + (uint32_t)((s % 3) * SEGB);

#pragma unroll
        for (int kc = 0; kc < 4; ++kc) {
            const uint32_t kb = (uint32_t)(kc * 32);

            uint32_t a[2][4];
#pragma unroll
            for (int m = 0; m < 2; ++m)
                ldmx4(a[m][0], a[m][1], a[m][2], a[m][3], slot + aoff[m] + kb);

#pragma unroll
            for (int j = 0; j < 3; ++j) {
                uint32_t b0, b1, b2, b3;
                ldmx4(b0, b1, b2, b3, slot + bro[j] + kb);
                mma16816(acc[0][2 * j],     a[0], b0, b1);
                mma16816(acc[1][2 * j],     a[1], b0, b1);
                mma16816(acc[0][2 * j + 1], a[0], b2, b3);
                mma16816(acc[1][2 * j + 1], a[1], b2, b3);
            }
            if (wn == 0) {  // 7th chunk, first warp column only
                uint32_t e0, e1;
                ldmx2(e0, e1, slot + brx + kb);
                mma16816(acc[0][6], a[0], e0, e1);
                mma16816(acc[1][6], a[1], e0, e1);
            }
        }
    }

    // ---- epilogue: bias + stores ----
    const int nchunks = (wn == 0) ? 7 : 6;
#pragma unroll
    for (int m = 0; m < 2; ++m) {
        const int px = (wm * 2 + m) * 16 + g;
#pragma unroll
        for (int nc = 0; nc < 7; ++nc) {
            if (nc >= nchunks) break;
            const int oc = (cb0 + nc) * 8 + c4;
            if (oc < OC_) {
                float bz0 = *(float*)(smem + SM_BIAS + oc * 4);
                float bz1 = *(float*)(smem + SM_BIAS + (oc + 1) * 4);
                size_t base0 = (((size_t)(b * OC_ + oc)) * OH_ + y) * OW_ + x0;
                size_t base1 = base0 + (size_t)OH_ * OW_;
                out[base0 + px]     = acc[m][nc][0] + bz0;
                out[base1 + px]     = acc[m][nc][1] + bz1;
                out[base0 + px + 8] = acc[m][nc][2] + bz0;
                out[base1 + px + 8] = acc[m][nc][3] + bz1;
            }
        }
    }
}

// ---------------- launch ----------------
extern "C" void kernel_launch(void* const* d_in, const int* in_sizes, int n_in,
                              void* d_out, int out_size) {
    const float* pic  = (const float*)d_in[0];   // [8,25,256,256]
    const float* wt   = (const float*)d_in[1];   // [100,25,9,9]
    const float* bias = (const float*)d_in[2];   // [100]
    float* out = (float*)d_out;                  // [8,100,248,248]

    int nw = KH_ * 4 * NOC * QPITCH;
    prep_w<<<(nw + 255) / 256, 256>>>(wt);
    int na = B_ * H_ * 2 * 4 * MT * (QPITCH / 2);
    prep_a<<<(na + 255) / 256, 256>>>(pic);

    cudaFuncSetAttribute(conv_hmma, cudaFuncAttributeMaxDynamicSharedMemorySize, SMEM_TOTAL);
    dim3 grid(2, OH_, B_);
    conv_hmma<<<grid, NTHR, SMEM_TOTAL>>>(bias, out);
}

// round 12
// speedup vs baseline: 1.3226x; 1.3226x over previous
#include <cuda_runtime.h>
#include <cuda_fp16.h>
#include <cstdint>

// ---------------- problem constants ----------------
#define KH_ 9
#define KW_ 9
#define IC_ 25
#define OC_ 100
#define H_  256
#define W_  256
#define OH_ 248
#define OW_ 248
#define B_  8

// ---------------- GEMM config ----------------
#define KWP 10            // kw padded 9 -> 10
#define NOC 104           // oc padded 100 -> 104 (13 n8 chunks: 7 + 6 per warp col)
#define MT  128           // pixels per tile
#define APITCH 144        // fp16 elems per ic row (compact A)
#define AROWB (APITCH*2)  // 288 B
#define NTHR 256
#define NAROWS 26         // 25 ic + zero row for k-pad

// B half tiles: 128 k-elems (+8 pad), pitch 136 elems = 272 B (68-word stride)
#define HPITCH 136
#define HROWB  272
#define HTILE  (NOC*HROWB)       // 28288 B
#define NSEG   18                // 9 kh * 2 halves

// A buffer: even copy + odd-shift copy, double buffered by kh parity
#define ACOPY (NAROWS*AROWB)     // 7488
#define ABUF  (2*ACOPY)          // 14976
#define GA_P  264                // padded row length of pre-converted A

// smem layout (bytes)
#define SM_BIAS 0
#define SM_A    512                         // two A buffers (kh parity)
#define SM_B    (SM_A + 2*ABUF)             // 30464
#define SMEM_TOTAL (SM_B + 3*HTILE)         // 30464 + 84864 = 115328 -> 2 CTAs/SM

// fp16 weights: [kh][half][oc][k_local(136)]
__device__ __align__(16) __half g_w[KH_][2][NOC][HPITCH];
// pre-converted fp16 input, even + odd-shift parity copies
__device__ __align__(16) __half g_ae[B_][IC_][H_][GA_P];
__device__ __align__(16) __half g_ao[B_][IC_][H_][GA_P];

// ---------------- helpers ----------------
__device__ __forceinline__ uint32_t smem_u32(const void* p) {
    uint32_t a;
    asm("{ .reg .u64 t; cvta.to.shared.u64 t, %1; cvt.u32.u64 %0, t; }" : "=r"(a) : "l"(p));
    return a;
}

__device__ __forceinline__ uint32_t lds32(uint32_t a) {
    uint32_t v;
    asm volatile("ld.shared.b32 %0, [%1];" : "=r"(v) : "r"(a));
    return v;
}

__device__ __forceinline__ void ldmx4(uint32_t& r0, uint32_t& r1, uint32_t& r2,
                                      uint32_t& r3, uint32_t addr) {
    asm volatile("ldmatrix.sync.aligned.m8n8.x4.shared.b16 {%0,%1,%2,%3}, [%4];"
                 : "=r"(r0), "=r"(r1), "=r"(r2), "=r"(r3) : "r"(addr));
}

__device__ __forceinline__ void ldmx2(uint32_t& r0, uint32_t& r1, uint32_t addr) {
    asm volatile("ldmatrix.sync.aligned.m8n8.x2.shared.b16 {%0,%1}, [%2];"
                 : "=r"(r0), "=r"(r1) : "r"(addr));
}

__device__ __forceinline__ void mma16816(float* d, const uint32_t* a,
                                         uint32_t b0, uint32_t b1) {
    asm volatile(
        "mma.sync.aligned.m16n8k16.row.col.f32.f16.f16.f32 "
        "{%0,%1,%2,%3}, {%4,%5,%6,%7}, {%8,%9}, {%0,%1,%2,%3};"
        : "+f"(d[0]), "+f"(d[1]), "+f"(d[2]), "+f"(d[3])
        : "r"(a[0]), "r"(a[1]), "r"(a[2]), "r"(a[3]), "r"(b0), "r"(b1));
}

__device__ __forceinline__ void cpasync16(uint32_t dst, const void* src) {
    asm volatile("cp.async.cg.shared.global [%0], [%1], 16;"
                 :: "r"(dst), "l"(src));
}

// ---------------- prep: weights ----------------
__global__ void prep_w(const float* __restrict__ wt) {
    int idx = blockIdx.x * blockDim.x + threadIdx.x;
    const int n = KH_ * 2 * NOC * HPITCH;
    if (idx >= n) return;
    int kh   = idx / (2 * NOC * HPITCH);
    int rem  = idx % (2 * NOC * HPITCH);
    int h    = rem / (NOC * HPITCH);      rem %= (NOC * HPITCH);
    int oc   = rem / HPITCH;
    int kl   = rem % HPITCH;
    float w = 0.f;
    int k = h * 128 + kl;
    if (oc < OC_ && kl < 128 && k < IC_ * KWP) {
        int ic = k / KWP, kw = k % KWP;
        if (kw < KW_)
            w = wt[(((size_t)oc * IC_ + ic) * KH_ + kh) * KW_ + kw];
    }
    g_w[kh][h][oc][kl] = __float2half_rn(w);
}

// ---------------- prep: input fp16 parity copies ----------------
__global__ void prep_a(const float* __restrict__ pic) {
    const long long total = (long long)B_ * IC_ * H_ * GA_P;
    long long idx = (long long)blockIdx.x * blockDim.x + threadIdx.x;
    if (idx >= total) return;
    int c    = (int)(idx % GA_P);
    long long r = idx / GA_P;        // (b*IC + ic)*H + row
    const float* prow = pic + r * W_;
    __half ve = __float2half_rn(c < W_ ? prow[c] : 0.f);
    __half vo = __float2half_rn(c + 1 < W_ ? prow[c + 1] : 0.f);
    ((__half*)g_ae)[idx] = ve;
    ((__half*)g_ao)[idx] = vo;
}

// ---------------- main kernel ----------------
// block = 128 px x 104 oc of one output row (b, y).
// 8 warps: wm = wid&3 (2 m16-frags), wn = wid>>2 (7 or 6 n8-chunks).
// 18 pipelined segments: seg s -> kh=s>>1, half=s&1; ring-3 B halves,
// A double-buffered by kh parity, staging via cp.async at distance 2.
__global__ __launch_bounds__(NTHR, 2)
void conv_hmma(const float* __restrict__ bias,
               float* __restrict__ out) {
    extern __shared__ char smem[];
    const uint32_t sb = smem_u32(smem);
    const int tid = threadIdx.x;
    const int lid = tid & 31;
    const int wid = tid >> 5;
    const int wm = wid & 3;
    const int wn = wid >> 2;
    const int g  = lid >> 2;          // 0..7
    const int c4 = (lid & 3) << 1;    // 0,2,4,6
    const int x0 = blockIdx.x ? (OW_ - MT) : 0;
    const int y  = blockIdx.y;
    const int b  = blockIdx.z;

    // ---- init: zero both A buffers (pads + zero row persist), stage bias ----
#pragma unroll 1
    for (int i = tid; i < (2 * ABUF) / 16; i += NTHR)
        *(uint4*)(smem + SM_A + i * 16) = make_uint4(0, 0, 0, 0);
    if (tid < NOC)
        *(float*)(smem + SM_BIAS + tid * 4) = (tid < OC_) ? bias[tid] : 0.f;
    __syncthreads();   // zeroing visible before cp.async overwrites data region

    // ---- prologue: group 0 = A(kh=0) + B(seg 0); group 1 = B(seg 1) ----
    {
        // A(0): 2 parities * 25 ic * 17 x 16B
#pragma unroll 1
        for (int i = tid; i < 2 * IC_ * 17; i += NTHR) {
            int p  = i / (IC_ * 17);
            int r  = i % (IC_ * 17);
            int ic = r / 17;
            int ch = r % 17;
            const __half* src = (p ? &g_ao[0][0][0][0] : &g_ae[0][0][0][0])
                + ((((size_t)b * IC_ + ic) * H_) + y) * GA_P + x0 + ch * 8;
            cpasync16(sb + SM_A + (uint32_t)(p * ACOPY + ic * AROWB + ch * 16), src);
        }
        // B(seg 0)
#pragma unroll 1
        for (int i = tid; i < HTILE / 16; i += NTHR)
            cpasync16(sb + SM_B + (uint32_t)(i * 16), (const char*)(&g_w[0][0][0][0]) + i * 16);
        asm volatile("cp.async.commit_group;" ::: "memory");
        // B(seg 1)
#pragma unroll 1
        for (int i = tid; i < HTILE / 16; i += NTHR)
            cpasync16(sb + SM_B + (uint32_t)(HTILE + i * 16),
                      (const char*)(&g_w[0][1][0][0]) + i * 16);
        asm volatile("cp.async.commit_group;" ::: "memory");
    }

    // ldmatrix per-thread addresses (within a B half tile)
    const int cb0 = wn * 7;        // base n8 chunk: 0 (7 chunks) or 7 (6 chunks)
    const int grp = lid >> 3;      // 0..3
    const int tr  = lid & 7;
    uint32_t bro[3];
#pragma unroll
    for (int j = 0; j < 3; ++j)
        bro[j] = (uint32_t)(((cb0 + 2 * j + (grp >> 1)) * 8 + tr) * HROWB
                            + (grp & 1) * 16);
    const uint32_t brx = (uint32_t)((6 * 8 + (lid & 7)) * HROWB
                                    + ((lid >> 3) & 1) * 16);   // chunk 6 (wn0 only)

    float acc[2][7][4];
#pragma unroll
    for (int m = 0; m < 2; ++m)
#pragma unroll
        for (int n = 0; n < 7; ++n)
#pragma unroll
            for (int q = 0; q < 4; ++q)
                acc[m][n][q] = 0.f;

    // ---- pipelined main loop ----
#pragma unroll 1
    for (int s = 0; s < NSEG; ++s) {
        const int kh = s >> 1;
        const int hf = s & 1;

        if (s < NSEG - 2) {
            asm volatile("cp.async.wait_group 1;" ::: "memory");
        } else {
            asm volatile("cp.async.wait_group 0;" ::: "memory");
        }
        __syncthreads();

        // issue prefetch group for segment s+2 (B half + A when kh advances)
        if (s + 2 < NSEG) {
            const int s2 = s + 2;
            const char* bsrc = (const char*)(&g_w[s2 >> 1][s2 & 1][0][0]);
            const uint32_t bdst = sb + SM_B + (uint32_t)((s2 % 3) * HTILE);
#pragma unroll 1
            for (int i = tid; i < HTILE / 16; i += NTHR)
                cpasync16(bdst + (uint32_t)(i * 16), bsrc + i * 16);
            if ((s2 & 1) == 0) {
                const int kh2 = s2 >> 1;
                const uint32_t adst = sb + SM_A + (uint32_t)((kh2 & 1) * ABUF);
#pragma unroll 1
                for (int i = tid; i < 2 * IC_ * 17; i += NTHR) {
                    int p  = i / (IC_ * 17);
                    int r  = i % (IC_ * 17);
                    int ic = r / 17;
                    int ch = r % 17;
                    const __half* src = (p ? &g_ao[0][0][0][0] : &g_ae[0][0][0][0])
                        + ((((size_t)b * IC_ + ic) * H_) + (y + kh2)) * GA_P + x0 + ch * 8;
                    cpasync16(adst + (uint32_t)(p * ACOPY + ic * AROWB + ch * 16), src);
                }
            }
            asm volatile("cp.async.commit_group;" ::: "memory");
        }

        // ---- compute: 8 kc chunks on half hf ----
        const uint32_t abufb = sb + SM_A + (uint32_t)((kh & 1) * ABUF);
        const uint32_t abase = abufb + ((g & 1) ? (uint32_t)(ACOPY - 2) : 0u);
        uint32_t apx[2][2];
#pragma unroll
        for (int m = 0; m < 2; ++m)
#pragma unroll
            for (int h = 0; h < 2; ++h)
                apx[m][h] = abase + (uint32_t)(((wm * 2 + m) * 16 + g + h * 8) * 2);

        const uint32_t qb = sb + SM_B + (uint32_t)((s % 3) * HTILE);

#pragma unroll
        for (int kc = 0; kc < 8; ++kc) {
            const int k0 = hf * 128 + kc * 16 + c4;
            const int k1 = k0 + 8;
            const int ic0 = (k0 * 6554) >> 16;   // /10
            const int ic1 = (k1 * 6554) >> 16;
            const uint32_t koff0 = (uint32_t)(ic0 * AROWB + (k0 - ic0 * KWP) * 2);
            const uint32_t koff1 = (uint32_t)(ic1 * AROWB + (k1 - ic1 * KWP) * 2);

            uint32_t a[2][4];
#pragma unroll
            for (int m = 0; m < 2; ++m) {
                a[m][0] = lds32(apx[m][0] + koff0);
                a[m][1] = lds32(apx[m][1] + koff0);
                a[m][2] = lds32(apx[m][0] + koff1);
                a[m][3] = lds32(apx[m][1] + koff1);
            }

            const uint32_t kb = (uint32_t)(kc * 32);
#pragma unroll
            for (int j = 0; j < 3; ++j) {
                uint32_t b0, b1, b2, b3;
                ldmx4(b0, b1, b2, b3, qb + bro[j] + kb);
                mma16816(acc[0][2 * j],     a[0], b0, b1);
                mma16816(acc[1][2 * j],     a[1], b0, b1);
                mma16816(acc[0][2 * j + 1], a[0], b2, b3);
                mma16816(acc[1][2 * j + 1], a[1], b2, b3);
            }
            if (wn == 0) {  // 7th chunk, first warp column only
                uint32_t e0, e1;
                ldmx2(e0, e1, qb + brx + kb);
                mma16816(acc[0][6], a[0], e0, e1);
                mma16816(acc[1][6], a[1], e0, e1);
            }
        }
    }

    // ---- epilogue: bias + stores ----
    const int nchunks = (wn == 0) ? 7 : 6;
#pragma unroll
    for (int m = 0; m < 2; ++m) {
        const int px = (wm * 2 + m) * 16 + g;
#pragma unroll
        for (int nc = 0; nc < 7; ++nc) {
            if (nc >= nchunks) break;
            const int oc = (cb0 + nc) * 8 + c4;
            if (oc < OC_) {
                float bz0 = *(float*)(smem + SM_BIAS + oc * 4);
                float bz1 = *(float*)(smem + SM_BIAS + (oc + 1) * 4);
                size_t base0 = (((size_t)(b * OC_ + oc)) * OH_ + y) * OW_ + x0;
                size_t base1 = base0 + (size_t)OH_ * OW_;
                out[base0 + px]     = acc[m][nc][0] + bz0;
                out[base1 + px]     = acc[m][nc][1] + bz1;
                out[base0 + px + 8] = acc[m][nc][2] + bz0;
                out[base1 + px + 8] = acc[m][nc][3] + bz1;
            }
        }
    }
}

// ---------------- launch ----------------
extern "C" void kernel_launch(void* const* d_in, const int* in_sizes, int n_in,
                              void* d_out, int out_size) {
    const float* pic  = (const float*)d_in[0];   // [8,25,256,256]
    const float* wt   = (const float*)d_in[1];   // [100,25,9,9]
    const float* bias = (const float*)d_in[2];   // [100]
    float* out = (float*)d_out;                  // [8,100,248,248]

    int nw = KH_ * 2 * NOC * HPITCH;
    prep_w<<<(nw + 255) / 256, 256>>>(wt);
    long long na = (long long)B_ * IC_ * H_ * GA_P;
    prep_a<<<(int)((na + 255) / 256), 256>>>(pic);

    cudaFuncSetAttribute(conv_hmma, cudaFuncAttributeMaxDynamicSharedMemorySize, SMEM_TOTAL);
    dim3 grid(2, OH_, B_);
    conv_hmma<<<grid, NTHR, SMEM_TOTAL>>>(bias, out);
}

// round 13
// speedup vs baseline: 1.4188x; 1.0727x over previous
#include <cuda_runtime.h>
#include <cuda_fp16.h>
#include <cstdint>

// ---------------- problem constants ----------------
#define KH_ 9
#define KW_ 9
#define IC_ 25
#define OC_ 100
#define H_  256
#define W_  256
#define OH_ 248
#define OW_ 248
#define B_  8

// ---------------- GEMM config ----------------
#define KWP 10            // kw padded 9 -> 10
#define NOC 104           // oc padded 100 -> 104 (13 n8 chunks: 7 + 6 per warp col)
#define NTHR 512          // 16 warps; M = 256 px (2 output rows x 128)
#define NAROWS 26         // 25 ic + zero row for k-pad

// B full-K tiles: 256 k-elems (250 real + pad), pitch 264 = 528 B (4-bank stride)
#define BPITCH 264
#define BROWB  528
#define BTILE  (NOC*BROWB)       // 54912 B
#define NSEG   9                 // one segment per kh (full K)

// A: per input row, even + odd-shift parity copies; 4-slot ring keyed by row&3
#define APITCH 144
#define AROWB (APITCH*2)         // 288 B
#define ACOPY (NAROWS*AROWB)     // 7488
#define ASLOT (2*ACOPY)          // 14976
#define GA_P  264                // padded row length of pre-converted A

// smem layout (bytes)
#define SM_BIAS 0
#define SM_A    512                          // 4 A slots
#define SM_B    (SM_A + 4*ASLOT)             // 512 + 59904 = 60416
#define SMEM_TOTAL (SM_B + 3*BTILE)          // 60416 + 164736 = 225152

// fp16 weights: [kh][oc][k(264)]
__device__ __align__(16) __half g_w[KH_][NOC][BPITCH];
// pre-converted fp16 input, even + odd-shift parity copies
__device__ __align__(16) __half g_ae[B_][IC_][H_][GA_P];
__device__ __align__(16) __half g_ao[B_][IC_][H_][GA_P];

// ---------------- helpers ----------------
__device__ __forceinline__ uint32_t smem_u32(const void* p) {
    uint32_t a;
    asm("{ .reg .u64 t; cvta.to.shared.u64 t, %1; cvt.u32.u64 %0, t; }" : "=r"(a) : "l"(p));
    return a;
}

__device__ __forceinline__ uint32_t lds32(uint32_t a) {
    uint32_t v;
    asm volatile("ld.shared.b32 %0, [%1];" : "=r"(v) : "r"(a));
    return v;
}

__device__ __forceinline__ void ldmx4(uint32_t& r0, uint32_t& r1, uint32_t& r2,
                                      uint32_t& r3, uint32_t addr) {
    asm volatile("ldmatrix.sync.aligned.m8n8.x4.shared.b16 {%0,%1,%2,%3}, [%4];"
                 : "=r"(r0), "=r"(r1), "=r"(r2), "=r"(r3) : "r"(addr));
}

__device__ __forceinline__ void ldmx2(uint32_t& r0, uint32_t& r1, uint32_t addr) {
    asm volatile("ldmatrix.sync.aligned.m8n8.x2.shared.b16 {%0,%1}, [%2];"
                 : "=r"(r0), "=r"(r1) : "r"(addr));
}

__device__ __forceinline__ void mma16816(float* d, const uint32_t* a,
                                         uint32_t b0, uint32_t b1) {
    asm volatile(
        "mma.sync.aligned.m16n8k16.row.col.f32.f16.f16.f32 "
        "{%0,%1,%2,%3}, {%4,%5,%6,%7}, {%8,%9}, {%0,%1,%2,%3};"
        : "+f"(d[0]), "+f"(d[1]), "+f"(d[2]), "+f"(d[3])
        : "r"(a[0]), "r"(a[1]), "r"(a[2]), "r"(a[3]), "r"(b0), "r"(b1));
}

__device__ __forceinline__ void cpasync16(uint32_t dst, const void* src) {
    asm volatile("cp.async.cg.shared.global [%0], [%1], 16;"
                 :: "r"(dst), "l"(src));
}

// ---------------- prep: weights ----------------
__global__ void prep_w(const float* __restrict__ wt) {
    int idx = blockIdx.x * blockDim.x + threadIdx.x;
    const int n = KH_ * NOC * BPITCH;
    if (idx >= n) return;
    int kh = idx / (NOC * BPITCH);
    int rem = idx % (NOC * BPITCH);
    int oc = rem / BPITCH;
    int k  = rem % BPITCH;
    float w = 0.f;
    if (oc < OC_ && k < IC_ * KWP) {
        int ic = k / KWP, kw = k % KWP;
        if (kw < KW_)
            w = wt[(((size_t)oc * IC_ + ic) * KH_ + kh) * KW_ + kw];
    }
    g_w[kh][oc][k] = __float2half_rn(w);
}

// ---------------- prep: input fp16 parity copies ----------------
__global__ void prep_a(const float* __restrict__ pic) {
    const long long total = (long long)B_ * IC_ * H_ * GA_P;
    long long idx = (long long)blockIdx.x * blockDim.x + threadIdx.x;
    if (idx >= total) return;
    int c    = (int)(idx % GA_P);
    long long r = idx / GA_P;        // (b*IC + ic)*H + row
    const float* prow = pic + r * W_;
    __half ve = __float2half_rn(c < W_ ? prow[c] : 0.f);
    __half vo = __float2half_rn(c + 1 < W_ ? prow[c + 1] : 0.f);
    ((__half*)g_ae)[idx] = ve;
    ((__half*)g_ao)[idx] = vo;
}

// ---------------- main kernel ----------------
// block = 256 px (2 output rows x 128) x 104 oc.
// 16 warps: wm = wid&7 (rowi = wm>>2, wmr = wm&3 -> 2 m16-frags),
//           wn = wid>>3 (7 or 6 n8-chunks).
// 9 segments (one per kh, full K=256). B ring-3, A 4-slot ring (row&3),
// one new A input-row set staged per kh. cp.async prefetch distance 2.
__global__ __launch_bounds__(NTHR, 1)
void conv_hmma(const float* __restrict__ bias,
               float* __restrict__ out) {
    extern __shared__ char smem[];
    const uint32_t sb = smem_u32(smem);
    const int tid = threadIdx.x;
    const int lid = tid & 31;
    const int wid = tid >> 5;
    const int wm  = wid & 7;
    const int wn  = wid >> 3;
    const int rowi = wm >> 2;         // 0: output row y0, 1: output row y0+1
    const int wmr  = wm & 3;
    const int g  = lid >> 2;          // 0..7
    const int c4 = (lid & 3) << 1;    // 0,2,4,6
    const int x0 = blockIdx.x ? (OW_ - 128) : 0;
    const int y0 = blockIdx.y * 2;
    const int b  = blockIdx.z;

    // ---- init: zero A slots (pads + zero row persist), stage bias ----
#pragma unroll 1
    for (int i = tid; i < (4 * ASLOT) / 16; i += NTHR)
        *(uint4*)(smem + SM_A + i * 16) = make_uint4(0, 0, 0, 0);
    if (tid < NOC)
        *(float*)(smem + SM_BIAS + tid * 4) = (tid < OC_) ? bias[tid] : 0.f;
    __syncthreads();   // zeroing visible before cp.async overwrites data region

    // ---- A row staging lambda-equivalent (macro-ish inline) ----
    // stage input row r into slot (r&3): 2 parities * 25 ic * 17 x 16B
#define STAGE_A_ROW(r)                                                          \
    {                                                                           \
        const uint32_t adst = sb + SM_A + (uint32_t)(((r) & 3) * ASLOT);        \
        _Pragma("unroll 1")                                                     \
        for (int i = tid; i < 2 * IC_ * 17; i += NTHR) {                        \
            int p  = i / (IC_ * 17);                                            \
            int rr = i % (IC_ * 17);                                            \
            int ic = rr / 17;                                                   \
            int ch = rr % 17;                                                   \
            const __half* src = (p ? &g_ao[0][0][0][0] : &g_ae[0][0][0][0])     \
                + ((((size_t)b * IC_ + ic) * H_) + (r)) * GA_P + x0 + ch * 8;   \
            cpasync16(adst + (uint32_t)(p * ACOPY + ic * AROWB + ch * 16), src);\
        }                                                                       \
    }

#define STAGE_B(kh, slot)                                                       \
    {                                                                           \
        const char* bsrc = (const char*)(&g_w[(kh)][0][0]);                     \
        const uint32_t bdst = sb + SM_B + (uint32_t)((slot) * BTILE);           \
        _Pragma("unroll 1")                                                     \
        for (int i = tid; i < BTILE / 16; i += NTHR)                            \
            cpasync16(bdst + (uint32_t)(i * 16), bsrc + i * 16);                \
    }

    // ---- prologue ----
    // group 0: A rows y0, y0+1 + B(kh=0)
    STAGE_A_ROW(y0);
    STAGE_A_ROW(y0 + 1);
    STAGE_B(0, 0);
    asm volatile("cp.async.commit_group;" ::: "memory");
    // group 1: A row y0+2 + B(kh=1)
    STAGE_A_ROW(y0 + 2);
    STAGE_B(1, 1);
    asm volatile("cp.async.commit_group;" ::: "memory");

    // ldmatrix per-thread addresses (within a B tile)
    const int cb0 = wn * 7;        // base n8 chunk: 0 (7 chunks) or 7 (6 chunks)
    const int grp = lid >> 3;      // 0..3
    const int tr  = lid & 7;
    uint32_t bro[3];
#pragma unroll
    for (int j = 0; j < 3; ++j)
        bro[j] = (uint32_t)(((cb0 + 2 * j + (grp >> 1)) * 8 + tr) * BROWB
                            + (grp & 1) * 16);
    const uint32_t brx = (uint32_t)((6 * 8 + (lid & 7)) * BROWB
                                    + ((lid >> 3) & 1) * 16);   // chunk 6 (wn0 only)

    float acc[2][7][4];
#pragma unroll
    for (int m = 0; m < 2; ++m)
#pragma unroll
        for (int n = 0; n < 7; ++n)
#pragma unroll
            for (int q = 0; q < 4; ++q)
                acc[m][n][q] = 0.f;

    // ---- pipelined main loop: one segment per kh ----
#pragma unroll 1
    for (int s = 0; s < NSEG; ++s) {
        if (s < NSEG - 2) {
            asm volatile("cp.async.wait_group 1;" ::: "memory");
        } else {
            asm volatile("cp.async.wait_group 0;" ::: "memory");
        }
        __syncthreads();

        // prefetch segment s+2: B(kh=s+2) + new A input row y0+s+3
        if (s + 2 < NSEG) {
            STAGE_B(s + 2, (s + 2) % 3);
            STAGE_A_ROW(y0 + s + 3);
            asm volatile("cp.async.commit_group;" ::: "memory");
        }

        // ---- compute: 16 kc chunks, full K ----
        const int arow = y0 + s + rowi;                 // this warp's input row
        const uint32_t abase = sb + SM_A + (uint32_t)((arow & 3) * ASLOT)
                             + ((g & 1) ? (uint32_t)(ACOPY - 2) : 0u);
        uint32_t apx[2][2];
#pragma unroll
        for (int m = 0; m < 2; ++m)
#pragma unroll
            for (int h = 0; h < 2; ++h)
                apx[m][h] = abase + (uint32_t)(((wmr * 2 + m) * 16 + g + h * 8) * 2);

        const uint32_t qb = sb + SM_B + (uint32_t)((s % 3) * BTILE);

#pragma unroll
        for (int kc = 0; kc < 16; ++kc) {
            const int k0 = kc * 16 + c4;
            const int k1 = k0 + 8;
            const int ic0 = (k0 * 6554) >> 16;   // /10
            const int ic1 = (k1 * 6554) >> 16;
            const uint32_t koff0 = (uint32_t)(ic0 * AROWB + (k0 - ic0 * KWP) * 2);
            const uint32_t koff1 = (uint32_t)(ic1 * AROWB + (k1 - ic1 * KWP) * 2);

            uint32_t a[2][4];
#pragma unroll
            for (int m = 0; m < 2; ++m) {
                a[m][0] = lds32(apx[m][0] + koff0);
                a[m][1] = lds32(apx[m][1] + koff0);
                a[m][2] = lds32(apx[m][0] + koff1);
                a[m][3] = lds32(apx[m][1] + koff1);
            }

            const uint32_t kb = (uint32_t)(kc * 32);
#pragma unroll
            for (int j = 0; j < 3; ++j) {
                uint32_t b0, b1, b2, b3;
                ldmx4(b0, b1, b2, b3, qb + bro[j] + kb);
                mma16816(acc[0][2 * j],     a[0], b0, b1);
                mma16816(acc[1][2 * j],     a[1], b0, b1);
                mma16816(acc[0][2 * j + 1], a[0], b2, b3);
                mma16816(acc[1][2 * j + 1], a[1], b2, b3);
            }
            if (wn == 0) {  // 7th chunk, first warp column only
                uint32_t e0, e1;
                ldmx2(e0, e1, qb + brx + kb);
                mma16816(acc[0][6], a[0], e0, e1);
                mma16816(acc[1][6], a[1], e0, e1);
            }
        }
    }

    // ---- epilogue: bias + stores ----
    const int nchunks = (wn == 0) ? 7 : 6;
    const int oy = y0 + rowi;
#pragma unroll
    for (int m = 0; m < 2; ++m) {
        const int px = (wmr * 2 + m) * 16 + g;
#pragma unroll
        for (int nc = 0; nc < 7; ++nc) {
            if (nc >= nchunks) break;
            const int oc = (cb0 + nc) * 8 + c4;
            if (oc < OC_) {
                float bz0 = *(float*)(smem + SM_BIAS + oc * 4);
                float bz1 = *(float*)(smem + SM_BIAS + (oc + 1) * 4);
                size_t base0 = (((size_t)(b * OC_ + oc)) * OH_ + oy) * OW_ + x0;
                size_t base1 = base0 + (size_t)OH_ * OW_;
                out[base0 + px]     = acc[m][nc][0] + bz0;
                out[base1 + px]     = acc[m][nc][1] + bz1;
                out[base0 + px + 8] = acc[m][nc][2] + bz0;
                out[base1 + px + 8] = acc[m][nc][3] + bz1;
            }
        }
    }
#undef STAGE_A_ROW
#undef STAGE_B
}

// ---------------- launch ----------------
extern "C" void kernel_launch(void* const* d_in, const int* in_sizes, int n_in,
                              void* d_out, int out_size) {
    const float* pic  = (const float*)d_in[0];   // [8,25,256,256]
    const float* wt   = (const float*)d_in[1];   // [100,25,9,9]
    const float* bias = (const float*)d_in[2];   // [100]
    float* out = (float*)d_out;                  // [8,100,248,248]

    int nw = KH_ * NOC * BPITCH;
    prep_w<<<(nw + 255) / 256, 256>>>(wt);
    long long na = (long long)B_ * IC_ * H_ * GA_P;
    prep_a<<<(int)((na + 255) / 256), 256>>>(pic);

    cudaFuncSetAttribute(conv_hmma, cudaFuncAttributeMaxDynamicSharedMemorySize, SMEM_TOTAL);
    dim3 grid(2, OH_ / 2, B_);
    conv_hmma<<<grid, NTHR, SMEM_TOTAL>>>(bias, out);
}